// round 1
// baseline (speedup 1.0000x reference)
#include <cuda_runtime.h>
#include <cuda_bf16.h>
#include <math.h>

#define B_   2
#define L_   1024
#define DM   2048
#define DI   4096
#define DS   16
#define DCONV 4
#define DTR  128
#define T_   (B_*L_)        // 2048 tokens
#define NX   160            // dt_rank + 2*d_state
#define NXPAD 256
#define KSPLITS 8

// ---------------- scratch (static __device__ arrays; no allocation) ----------------
__device__ float g_hs   [(size_t)T_*DM];        // 16 MB  normalized hidden
__device__ float g_xz   [(size_t)T_*2*DI];      // 64 MB  in_proj output
__device__ float g_xc   [(size_t)T_*DI];        // 32 MB  conv+silu(x)
__device__ float g_xdblp[(size_t)KSPLITS*T_*NXPAD]; // 16 MB split-K partials
__device__ float g_xdbl [(size_t)T_*NX];        // 1.3 MB
__device__ float g_dt   [(size_t)T_*DI];        // 32 MB
__device__ float g_ys   [(size_t)T_*DI];        // 32 MB  scan out -> gated y

// ---------------- helpers ----------------
__device__ __forceinline__ float siluf(float x) {
    return x / (1.0f + expf(-x));
}
__device__ __forceinline__ float softplusf(float x) {
    return (x > 20.0f) ? x : log1pf(expf(x));
}

// ---------------- 1) fused add + RMSNorm ----------------
// one block per token; 256 threads, 8 cols each (DM=2048)
__global__ void addnorm_kernel(const float* __restrict__ h, const float* __restrict__ r,
                               const float* __restrict__ w, float* __restrict__ resid_out,
                               float* __restrict__ hs) {
    int t = blockIdx.x;
    int tid = threadIdx.x;
    const float* hp = h + (size_t)t * DM;
    const float* rp = r + (size_t)t * DM;
    float v[8];
    float ss = 0.f;
#pragma unroll
    for (int i = 0; i < 8; i++) {
        int c = tid + i * 256;
        float x = hp[c] + rp[c];
        v[i] = x;
        ss += x * x;
    }
    __shared__ float red[256];
    red[tid] = ss;
    __syncthreads();
    for (int s = 128; s > 0; s >>= 1) {
        if (tid < s) red[tid] += red[tid + s];
        __syncthreads();
    }
    float scale = rsqrtf(red[0] / (float)DM + 1e-5f);
#pragma unroll
    for (int i = 0; i < 8; i++) {
        int c = tid + i * 256;
        if (resid_out) resid_out[(size_t)t * DM + c] = v[i];
        hs[(size_t)t * DM + c] = v[i] * scale * w[c];
    }
}

// ---------------- 2) generic SGEMM: C[M,N] = A[M,K] * W[N,K]^T ----------------
// 128x128 block tile, BK=8, 256 threads, 8x8 per thread. Optional split-K via blockIdx.z
// (each z writes its own C slab). Optional N-guard (for N=160) and softplus+bias epilogue.
template<int EPI, bool NGUARD>
__global__ void __launch_bounds__(256, 2)
sgemm128(const float* __restrict__ A, const float* __restrict__ Wt, float* __restrict__ C,
         int M, int Nlog, int lda, int ldw, int ldc, int ksplit,
         const float* __restrict__ bias) {
    __shared__ float As[8][132];
    __shared__ float Bs[8][132];
    int tid = threadIdx.x;
    int m0 = blockIdx.y * 128, n0 = blockIdx.x * 128;
    int kstart = blockIdx.z * ksplit;
    int kend = kstart + ksplit;
    float* Cb = C + (size_t)blockIdx.z * M * ldc;

    int row = tid >> 1;
    int k4 = (tid & 1) * 4;
    const float* Ag = A + (size_t)(m0 + row) * lda + kstart + k4;
    bool wvalid = true;
    if (NGUARD) wvalid = (n0 + row) < Nlog;
    const float* Wg = Wt + (size_t)(n0 + row) * ldw + kstart + k4;

    int tx = tid & 15, ty = tid >> 4;
    float acc[8][8];
#pragma unroll
    for (int i = 0; i < 8; i++)
#pragma unroll
        for (int j = 0; j < 8; j++) acc[i][j] = 0.f;

    for (int kt = kstart; kt < kend; kt += 8) {
        float4 av = *(const float4*)Ag;
        float4 wv = make_float4(0.f, 0.f, 0.f, 0.f);
        if (!NGUARD || wvalid) wv = *(const float4*)Wg;
        As[k4 + 0][row] = av.x;
        As[k4 + 1][row] = av.y;
        As[k4 + 2][row] = av.z;
        As[k4 + 3][row] = av.w;
        Bs[k4 + 0][row] = wv.x;
        Bs[k4 + 1][row] = wv.y;
        Bs[k4 + 2][row] = wv.z;
        Bs[k4 + 3][row] = wv.w;
        __syncthreads();
#pragma unroll
        for (int kk = 0; kk < 8; kk++) {
            float4 a0 = *(const float4*)&As[kk][ty * 8];
            float4 a1 = *(const float4*)&As[kk][ty * 8 + 4];
            float4 b0 = *(const float4*)&Bs[kk][tx * 8];
            float4 b1 = *(const float4*)&Bs[kk][tx * 8 + 4];
            float a[8] = {a0.x, a0.y, a0.z, a0.w, a1.x, a1.y, a1.z, a1.w};
            float b[8] = {b0.x, b0.y, b0.z, b0.w, b1.x, b1.y, b1.z, b1.w};
#pragma unroll
            for (int i = 0; i < 8; i++)
#pragma unroll
                for (int j = 0; j < 8; j++) acc[i][j] = fmaf(a[i], b[j], acc[i][j]);
        }
        __syncthreads();
        Ag += 8;
        Wg += 8;
    }

#pragma unroll
    for (int i = 0; i < 8; i++) {
        int m = m0 + ty * 8 + i;
        float* crow = Cb + (size_t)m * ldc + n0 + tx * 8;
#pragma unroll
        for (int j = 0; j < 8; j++) {
            int n = n0 + tx * 8 + j;
            float v = acc[i][j];
            if (EPI == 1) v = softplusf(v + bias[n]);
            if (!NGUARD || n < Nlog) crow[j] = v;
        }
    }
}

// ---------------- 3) depthwise causal conv (width 4) + SiLU ----------------
// x lives in g_xz[:, 0:DI]; output -> g_xc. grid (DI/256, L/64, B), 256 threads.
__global__ void conv_silu_kernel(const float* __restrict__ xz,
                                 const float* __restrict__ cw,
                                 const float* __restrict__ cb,
                                 float* __restrict__ xc) {
    int d = blockIdx.x * 256 + threadIdx.x;
    int b = blockIdx.z;
    int l0 = blockIdx.y * 64;
    float c0 = cw[d * 4 + 0], c1 = cw[d * 4 + 1], c2 = cw[d * 4 + 2], c3 = cw[d * 4 + 3];
    float bias = cb[d];
    // window registers for x[l-3], x[l-2], x[l-1]
    float w0 = 0.f, w1 = 0.f, w2 = 0.f;
#pragma unroll
    for (int j = 3; j >= 1; j--) {
        int l = l0 - j;
        float v = (l >= 0) ? xz[((size_t)(b * L_ + l)) * (2 * DI) + d] : 0.f;
        if (j == 3) w0 = v;
        else if (j == 2) w1 = v;
        else w2 = v;
    }
    for (int i = 0; i < 64; i++) {
        int l = l0 + i;
        float xv = xz[((size_t)(b * L_ + l)) * (2 * DI) + d];
        float a = bias + c0 * w0 + c1 * w1 + c2 * w2 + c3 * xv;
        xc[((size_t)(b * L_ + l)) * DI + d] = siluf(a);
        w0 = w1; w1 = w2; w2 = xv;
    }
}

// ---------------- 4) split-K reduce for x_dbl ----------------
__global__ void xdbl_reduce_kernel(const float* __restrict__ part, float* __restrict__ out) {
    int idx = blockIdx.x * 256 + threadIdx.x;
    if (idx >= T_ * NX) return;
    int t = idx / NX;
    int n = idx - t * NX;
    float s = 0.f;
#pragma unroll
    for (int z = 0; z < KSPLITS; z++)
        s += part[((size_t)z * T_ + t) * NXPAD + n];
    out[idx] = s;
}

// ---------------- 5) selective scan ----------------
// 16 lanes per (b,d) channel (one lane per state). 128 threads = 8 channels/block.
__global__ void scan_kernel(const float* __restrict__ dt, const float* __restrict__ xc,
                            const float* __restrict__ xdbl, const float* __restrict__ A_log,
                            float* __restrict__ ys) {
    int tid = threadIdx.x;
    int lane = tid & 15;
    int grp = tid >> 4;
    int ch = blockIdx.x * 8 + grp;           // 0..B*DI-1
    int b = ch >> 12;                         // / DI (DI=4096)
    int d = ch & (DI - 1);
    float Aval = -expf(A_log[d * DS + lane]); // exact vs reference's -exp(A_log)
    float h = 0.f;
    size_t baseRow = (size_t)b * L_;
    for (int l = 0; l < L_; l++) {
        size_t t = baseRow + l;
        float dtv = dt[t * DI + d];
        float xv = xc[t * DI + d];
        const float* xd = xdbl + t * NX;
        float bs = xd[DTR + lane];
        float cs = xd[DTR + DS + lane];
        float dA = __expf(dtv * Aval);        // arg <= 0, dA in (0,1]
        h = fmaf(dA, h, dtv * xv * bs);
        float yp = h * cs;
        yp += __shfl_xor_sync(0xffffffffu, yp, 8);
        yp += __shfl_xor_sync(0xffffffffu, yp, 4);
        yp += __shfl_xor_sync(0xffffffffu, yp, 2);
        yp += __shfl_xor_sync(0xffffffffu, yp, 1);
        if (lane == 0) ys[t * DI + d] = yp;
    }
}

// ---------------- 6) gating: y = (ys + xc*D) * silu(z) ----------------
__global__ void gate_kernel(const float* __restrict__ xz, const float* __restrict__ xc,
                            const float* __restrict__ Dp, float* __restrict__ ys) {
    size_t idx = (size_t)blockIdx.x * 256 + threadIdx.x;
    size_t t = idx / DI;
    int d = (int)(idx - t * DI);
    float z = xz[t * (2 * DI) + DI + d];
    float y = (ys[idx] + xc[idx] * Dp[d]) * siluf(z);
    ys[idx] = y;
}

// ---------------- launch ----------------
extern "C" void kernel_launch(void* const* d_in, const int* in_sizes, int n_in,
                              void* d_out, int out_size) {
    const float* hidden   = (const float*)d_in[0];
    const float* residual = (const float*)d_in[1];
    const float* norm_w   = (const float*)d_in[2];
    const float* in_proj  = (const float*)d_in[3];   // [8192, 2048]
    const float* conv_w   = (const float*)d_in[4];   // [4096, 4]
    const float* conv_b   = (const float*)d_in[5];
    const float* x_proj   = (const float*)d_in[6];   // [160, 4096]
    const float* dt_proj  = (const float*)d_in[7];   // [4096, 128]
    const float* dt_bias  = (const float*)d_in[8];
    const float* A_log    = (const float*)d_in[9];   // [4096, 16]
    const float* D_param  = (const float*)d_in[10];
    const float* out_proj = (const float*)d_in[11];  // [2048, 4096]

    float* out = (float*)d_out;
    float* resid_out = (out_size >= 2 * T_ * DM) ? out + (size_t)T_ * DM : nullptr;

    float* hs = g_hs;
    float* xz = g_xz;
    float* xc = g_xc;
    float* xdblp = g_xdblp;
    float* xdbl = g_xdbl;
    float* dt = g_dt;
    float* ys = g_ys;

    // 1) add + rmsnorm
    addnorm_kernel<<<T_, 256>>>(hidden, residual, norm_w, resid_out, hs);

    // 2) xz = hs @ in_proj^T : M=2048, N=8192, K=2048
    sgemm128<0, false><<<dim3(2 * DI / 128, T_ / 128, 1), 256>>>(
        hs, in_proj, xz, T_, 2 * DI, DM, DM, 2 * DI, DM, nullptr);

    // 3) depthwise conv + silu
    conv_silu_kernel<<<dim3(DI / 256, L_ / 64, B_), 256>>>(xz, conv_w, conv_b, xc);

    // 4) x_dbl = xc @ x_proj^T : M=2048, N=160 (padded 256), K=4096, split-K=8
    sgemm128<0, true><<<dim3(NXPAD / 128, T_ / 128, KSPLITS), 256>>>(
        xc, x_proj, xdblp, T_, NX, DI, DI, NXPAD, DI / KSPLITS, nullptr);
    xdbl_reduce_kernel<<<(T_ * NX + 255) / 256, 256>>>(xdblp, xdbl);

    // 5) dt = softplus(x_dbl[:, :128] @ dt_proj^T + b) : M=2048, N=4096, K=128
    sgemm128<1, false><<<dim3(DI / 128, T_ / 128, 1), 256>>>(
        xdbl, dt_proj, dt, T_, DI, NX, DTR, DI, DTR, dt_bias);

    // 6) selective scan
    scan_kernel<<<B_ * DI / 8, 128>>>(dt, xc, xdbl, A_log, ys);

    // 7) gate
    gate_kernel<<<(int)(((size_t)T_ * DI) / 256), 256>>>(xz, xc, D_param, ys);

    // 8) out = y @ out_proj^T : M=2048, N=2048, K=4096
    sgemm128<0, false><<<dim3(DM / 128, T_ / 128, 1), 256>>>(
        ys, out_proj, out, T_, DM, DI, DI, DM, DI, nullptr);
}